// round 4
// baseline (speedup 1.0000x reference)
#include <cuda_runtime.h>
#include <cstdint>
#include <cstddef>

// Problem dims (fixed by the reference)
#define Bt 1024
#define Tt 512
#define Ii 45
#define Hh 128
#define Oo 45

#define NB  7            // batch rows per CTA (8th lane is zero pad)
#define NTH 256          // 2 threads per hidden unit j: lane-pair split over k
#define NBLK ((Bt + NB - 1) / NB)   // 147 CTAs

// Shared-memory layout (in floats)
#define XROWS 48                           // Ii padded (rows 45..47 zero)
#define OFF_WHH  0                         // W_hh transposed: [k][j], 128*128
#define OFF_WIH  (Hh * Hh)                 // W_ih transposed: [i][j], 48*128 (padded)
#define OFF_BIAS (OFF_WIH + XROWS * Hh)    // b_ih + b_hh, 128
#define OFF_H    (OFF_BIAS + Hh)           // h double buffer: [2][128][8]
#define OFF_X    (OFF_H + 2 * Hh * 8)      // x stage double buffer: [2][48][8]
#define SMEM_FLOATS (OFF_X + 2 * XROWS * 8)
#define SMEM_BYTES  (SMEM_FLOATS * 4)      // ~101 KB

typedef unsigned long long ull;

// Packed fp32x2 FMA (sm_100+): acc = a*b + acc, elementwise on 2 packed floats
__device__ __forceinline__ void fma2(ull& acc, ull a, ull b) {
    asm("fma.rn.f32x2 %0, %1, %2, %0;" : "+l"(acc) : "l"(a), "l"(b));
}
__device__ __forceinline__ void add2(ull& acc, ull a) {
    asm("add.rn.f32x2 %0, %0, %1;" : "+l"(acc) : "l"(a));
}
__device__ __forceinline__ ull pack2(float f) {
    ull d; unsigned u = __float_as_uint(f);
    asm("mov.b64 %0, {%1, %1};" : "=l"(d) : "r"(u));
    return d;
}
__device__ __forceinline__ float2 unpack2(ull d) {
    unsigned lo, hi;
    asm("mov.b64 {%0, %1}, %2;" : "=r"(lo), "=r"(hi) : "l"(d));
    return make_float2(__uint_as_float(lo), __uint_as_float(hi));
}

// tanh(x) = 1 - 2/(exp(2x)+1): 2 MUFU + few FMA, ~1e-6 abs err,
// exact saturation at +/-1 for large |x| (exp->inf / exp->0).
__device__ __forceinline__ float fast_tanh(float x) {
    float e = __expf(2.0f * x);
    return 1.0f - __fdividef(2.0f, e + 1.0f);
}

__global__ void __launch_bounds__(NTH, 1)
rnn_fused_kernel(const float* __restrict__ x,
                 const float* __restrict__ W_ih,
                 const float* __restrict__ b_ih,
                 const float* __restrict__ W_hh,
                 const float* __restrict__ b_hh,
                 const float* __restrict__ W_fc,
                 const float* __restrict__ b_fc,
                 float* __restrict__ out)
{
    extern __shared__ float sm[];
    float* whh_t  = sm + OFF_WHH;
    float* wih_t  = sm + OFF_WIH;
    float* bias_s = sm + OFF_BIAS;
    float* hT     = sm + OFF_H;     // [buf][k][b], b padded to 8 (lane 7 = 0)
    float* xT     = sm + OFF_X;     // [buf][i][b], i padded to 48, b padded to 8

    const int tid = threadIdx.x;
    const int j   = tid >> 1;       // hidden unit owned by this lane pair
    const int par = tid & 1;        // k-half: par0 -> k[0,64)/i[0,23), par1 -> k[64,128)/i[23,46)
    const int rowBase = blockIdx.x * NB;

    // ---- Stage weights into SMEM (transposed) ----
    for (int idx = tid; idx < Hh * Hh; idx += NTH) {
        int jj = idx >> 7;
        int kk = idx & (Hh - 1);
        whh_t[kk * Hh + jj] = W_hh[idx];        // whh_t[k][j] = W_hh[j][k]
    }
    for (int idx = tid; idx < XROWS * Hh; idx += NTH) wih_t[idx] = 0.0f;
    for (int idx = tid; idx < 2 * Hh * 8; idx += NTH) hT[idx] = 0.0f;
    for (int idx = tid; idx < 2 * XROWS * 8; idx += NTH) xT[idx] = 0.0f;
    if (tid < Hh) bias_s[tid] = b_ih[tid] + b_hh[tid];
    __syncthreads();
    for (int idx = tid; idx < Hh * Ii; idx += NTH) {
        int jj = idx / Ii;
        int ii = idx - jj * Ii;
        wih_t[ii * Hh + jj] = W_ih[idx];        // wih_t[i][j] = W_ih[j][i]
    }
    __syncthreads();

    // ---- Pull this thread's weight column into registers ----
    float whh_r[64];
    #pragma unroll
    for (int kk = 0; kk < 64; ++kk)
        whh_r[kk] = whh_t[(par * 64 + kk) * Hh + j];
    float wih_r[23];
    #pragma unroll
    for (int ii = 0; ii < 23; ++ii)
        wih_r[ii] = wih_t[(par * 23 + ii) * Hh + j];   // par1 row 45 is zero pad

    // ---- x stager: 256 threads cover NB*Ii = 315 elems (<=2 each) ----
    const int e0 = tid, e1 = tid + NTH;
    const bool a0 = e0 < NB * Ii, a1 = e1 < NB * Ii;
    const int b0 = a0 ? e0 / Ii : 0, b1 = a1 ? e1 / Ii : 0;
    const int i0 = e0 - b0 * Ii,    i1 = e1 - b1 * Ii;
    const bool val0 = a0 && (rowBase + b0 < Bt);
    const bool val1 = a1 && (rowBase + b1 < Bt);
    const float* g0 = x + ((size_t)(rowBase + b0) * Tt) * Ii + i0;
    const float* g1 = x + ((size_t)(rowBase + b1) * Tt) * Ii + i1;
    const int s0 = i0 * 8 + b0, s1 = i1 * 8 + b1;

    // Stage x for t = 0 into buffer 0
    if (a0) xT[s0] = val0 ? g0[0] : 0.0f;
    if (a1) xT[s1] = val1 ? g1[0] : 0.0f;
    __syncthreads();

    const ull bias2 = (par == 0) ? pack2(bias_s[j]) : 0ull;  // bias added once per pair

    for (int t = 0; t < Tt; ++t) {
        const int cur = t & 1;
        const float* hcur = hT + cur * (Hh * 8) + par * (64 * 8);
        const float* xcur = xT + cur * (XROWS * 8) + par * (23 * 8);

        // Prefetch next-step x (latency hidden behind the FMA loops below)
        float n0 = 0.0f, n1 = 0.0f;
        if (t + 1 < Tt) {
            const int off = (t + 1) * Ii;
            if (val0) n0 = g0[off];
            if (val1) n1 = g1[off];
        }

        // Packed accumulators over batch rows: (0,1) (2,3) (4,5) (6,pad)
        ull acc01 = bias2, acc23 = bias2, acc45 = bias2, acc67 = bias2;

        // Input contribution (this thread's 23 i-slice; par1 slice ends in zero pad)
        #pragma unroll
        for (int ii = 0; ii < 23; ++ii) {
            const ull ww = pack2(wih_r[ii]);
            const ulonglong2 xa = *reinterpret_cast<const ulonglong2*>(xcur + ii * 8);
            const ulonglong2 xb = *reinterpret_cast<const ulonglong2*>(xcur + ii * 8 + 4);
            fma2(acc01, ww, xa.x);
            fma2(acc23, ww, xa.y);
            fma2(acc45, ww, xb.x);
            fma2(acc67, ww, xb.y);
        }

        // Recurrent contribution (this thread's 64 k-slice)
        #pragma unroll
        for (int kk = 0; kk < 64; ++kk) {
            const ull ww = pack2(whh_r[kk]);
            const ulonglong2 ha = *reinterpret_cast<const ulonglong2*>(hcur + kk * 8);
            const ulonglong2 hb = *reinterpret_cast<const ulonglong2*>(hcur + kk * 8 + 4);
            fma2(acc01, ww, ha.x);
            fma2(acc23, ww, ha.y);
            fma2(acc45, ww, hb.x);
            fma2(acc67, ww, hb.y);
        }

        // Pair-reduce across lane parity (same warp, lane^1) — no barrier needed
        add2(acc01, __shfl_xor_sync(0xffffffffu, acc01, 1));
        add2(acc23, __shfl_xor_sync(0xffffffffu, acc23, 1));
        add2(acc45, __shfl_xor_sync(0xffffffffu, acc45, 1));
        add2(acc67, __shfl_xor_sync(0xffffffffu, acc67, 1));

        // tanh + store h_new, split across the pair: par0 -> rows 0..3, par1 -> rows 4..6
        float* hn = hT + (cur ^ 1) * (Hh * 8) + j * 8 + par * 4;
        float4 o;
        if (par == 0) {
            const float2 p01 = unpack2(acc01);
            const float2 p23 = unpack2(acc23);
            o.x = fast_tanh(p01.x); o.y = fast_tanh(p01.y);
            o.z = fast_tanh(p23.x); o.w = fast_tanh(p23.y);
        } else {
            const float2 p45 = unpack2(acc45);
            const float2 p67 = unpack2(acc67);
            o.x = fast_tanh(p45.x); o.y = fast_tanh(p45.y);
            o.z = fast_tanh(p67.x); o.w = 0.0f;       // keep pad lane at 0
        }
        *reinterpret_cast<float4*>(hn) = o;

        // Store prefetched x into the other buffer (pad lanes stay 0)
        float* xn = xT + (cur ^ 1) * (XROWS * 8);
        if (a0) xn[s0] = n0;
        if (a1) xn[s1] = n1;

        __syncthreads();   // one barrier per step: next buffers fully written
    }

    // ---- Final FC: out[b][o] = b_fc[o] + sum_j W_fc[o][j] * h_last[b][j] ----
    // Tt is even, so the last write (t = 511) landed in buffer 0.
    const float* hlast = hT;
    for (int idx = tid; idx < NB * Oo; idx += NTH) {
        const int b = idx / Oo;
        const int o = idx - b * Oo;
        const int row = rowBase + b;
        if (row < Bt) {
            float s = b_fc[o];
            const float* wp = W_fc + o * Hh;
            #pragma unroll 8
            for (int jj = 0; jj < Hh; ++jj)
                s = fmaf(wp[jj], hlast[jj * 8 + b], s);
            out[row * Oo + o] = s;
        }
    }
}

extern "C" void kernel_launch(void* const* d_in, const int* in_sizes, int n_in,
                              void* d_out, int out_size)
{
    const float* x   = (const float*)d_in[0];
    const float* Wih = (const float*)d_in[1];
    const float* bih = (const float*)d_in[2];
    const float* Whh = (const float*)d_in[3];
    const float* bhh = (const float*)d_in[4];
    const float* Wfc = (const float*)d_in[5];
    const float* bfc = (const float*)d_in[6];
    float* out = (float*)d_out;

    cudaFuncSetAttribute(rnn_fused_kernel,
                         cudaFuncAttributeMaxDynamicSharedMemorySize, SMEM_BYTES);
    rnn_fused_kernel<<<NBLK, NTH, SMEM_BYTES>>>(x, Wih, bih, Whh, bhh, Wfc, bfc, out);
}

// round 5
// speedup vs baseline: 1.0811x; 1.0811x over previous
#include <cuda_runtime.h>
#include <cstdint>
#include <cstddef>

// Problem dims (fixed by the reference)
#define Bt 1024
#define Tt 512
#define Ii 45
#define Hh 128
#define Oo 45

#define NB  7            // batch rows per CTA (row 7 is pad)
#define NTH 256          // 8 warps: warps 0-3 -> rows 0-3, warps 4-7 -> rows 4-7
#define NBLK ((Bt + NB - 1) / NB)   // 147 CTAs

#define K4 32            // 128 k packed as float4 over k
#define I4 12            // 45 i padded to 48, packed as float4 over i

// Shared-memory layout (in floats)
#define OFF_WHH4 0                              // [k4][j] float4 : 32*128*4
#define OFF_WIH4 (K4 * Hh * 4)                  // [i4][j] float4 : 12*128*4
#define OFF_BIAS (OFF_WIH4 + I4 * Hh * 4)       // 128
#define OFF_H    (OFF_BIAS + Hh)                // [2][128][8]
#define OFF_X    (OFF_H + 2 * Hh * 8)           // [2][48][8]
#define SMEM_FLOATS (OFF_X + 2 * 48 * 8)
#define SMEM_BYTES  (SMEM_FLOATS * 4)           // ~102 KB

// tanh(x) = 1 - 2/(exp(2x)+1): 2 MUFU + few FMA, ~1e-6 abs err,
// exact saturation at +/-1 for large |x|.
__device__ __forceinline__ float fast_tanh(float x) {
    float e = __expf(2.0f * x);
    return 1.0f - __fdividef(2.0f, e + 1.0f);
}

__global__ void __launch_bounds__(NTH, 1)
rnn_fused_kernel(const float* __restrict__ x,
                 const float* __restrict__ W_ih,
                 const float* __restrict__ b_ih,
                 const float* __restrict__ W_hh,
                 const float* __restrict__ b_hh,
                 const float* __restrict__ W_fc,
                 const float* __restrict__ b_fc,
                 float* __restrict__ out)
{
    extern __shared__ float sm[];
    float* whh4   = sm + OFF_WHH4;  // float4-packed over k: [(k4*128 + j)*4 + (k&3)]
    float* wih4   = sm + OFF_WIH4;  // float4-packed over i
    float* bias_s = sm + OFF_BIAS;
    float* hT     = sm + OFF_H;     // [buf][k][b8]
    float* xT     = sm + OFF_X;     // [buf][i48][b8]

    const int tid = threadIdx.x;
    const int j   = tid & 127;      // hidden unit owned by this thread
    const int grp = tid >> 7;       // 0: batch rows 0-3, 1: rows 4-7 (row 7 pad)
    const int rowBase = blockIdx.x * NB;

    // ---- Stage weights into SMEM, k/i-packed float4, j-major within pack ----
    for (int idx = tid; idx < I4 * Hh * 4; idx += NTH) wih4[idx] = 0.0f;
    for (int idx = tid; idx < 2 * Hh * 8; idx += NTH) hT[idx] = 0.0f;
    for (int idx = tid; idx < 2 * 48 * 8; idx += NTH) xT[idx] = 0.0f;
    if (tid < Hh) bias_s[tid] = b_ih[tid] + b_hh[tid];
    for (int idx = tid; idx < Hh * Hh; idx += NTH) {
        int jj = idx >> 7;
        int kk = idx & (Hh - 1);
        whh4[((kk >> 2) * Hh + jj) * 4 + (kk & 3)] = W_hh[idx];
    }
    __syncthreads();   // wih4 zero-fill before scatter
    for (int idx = tid; idx < Hh * Ii; idx += NTH) {
        int jj = idx / Ii;
        int ii = idx - jj * Ii;
        wih4[((ii >> 2) * Hh + jj) * 4 + (ii & 3)] = W_ih[idx];
    }

    // ---- x stager: 256 threads cover NB*Ii = 315 elems (<=2 each) ----
    const int e0 = tid, e1 = tid + NTH;
    const bool a1 = e1 < NB * Ii;                 // e0 < 315 always (tid < 256)
    const int b0 = e0 / Ii, b1 = a1 ? e1 / Ii : 0;
    const int i0 = e0 - b0 * Ii, i1 = e1 - b1 * Ii;
    const bool val0 = (rowBase + b0 < Bt);
    const bool val1 = a1 && (rowBase + b1 < Bt);
    const float* g0 = x + ((size_t)(rowBase + b0) * Tt) * Ii + i0;
    const float* g1 = x + ((size_t)(rowBase + b1) * Tt) * Ii + i1;
    const int s0 = i0 * 8 + b0, s1 = i1 * 8 + b1;

    __syncthreads();

    // Stage x for t = 0 into buffer 0
    xT[s0] = val0 ? g0[0] : 0.0f;
    if (a1) xT[s1] = val1 ? g1[0] : 0.0f;
    __syncthreads();

    const float bi = bias_s[j];

    for (int t = 0; t < Tt; ++t) {
        const int cur = t & 1;
        const float* hc = hT + cur * (Hh * 8) + grp * 4;   // this group's 4 rows
        const float* xc = xT + cur * (48 * 8) + grp * 4;

        // Prefetch next-step x (hidden behind the FMA loops)
        float n0 = 0.0f, n1 = 0.0f;
        if (t + 1 < Tt) {
            const int off = (t + 1) * Ii;
            if (val0) n0 = g0[off];
            if (val1) n1 = g1[off];
        }

        float acc0 = bi, acc1 = bi, acc2 = bi, acc3 = bi;

        // Input contribution: 12 float4-packed i-steps
        #pragma unroll
        for (int i4 = 0; i4 < I4; ++i4) {
            const float4 w4 = *reinterpret_cast<const float4*>(wih4 + (i4 * Hh + j) * 4);
            const float4 x0 = *reinterpret_cast<const float4*>(xc + (i4 * 4 + 0) * 8);
            const float4 x1 = *reinterpret_cast<const float4*>(xc + (i4 * 4 + 1) * 8);
            const float4 x2 = *reinterpret_cast<const float4*>(xc + (i4 * 4 + 2) * 8);
            const float4 x3 = *reinterpret_cast<const float4*>(xc + (i4 * 4 + 3) * 8);
            acc0 = fmaf(w4.x, x0.x, acc0); acc1 = fmaf(w4.x, x0.y, acc1);
            acc2 = fmaf(w4.x, x0.z, acc2); acc3 = fmaf(w4.x, x0.w, acc3);
            acc0 = fmaf(w4.y, x1.x, acc0); acc1 = fmaf(w4.y, x1.y, acc1);
            acc2 = fmaf(w4.y, x1.z, acc2); acc3 = fmaf(w4.y, x1.w, acc3);
            acc0 = fmaf(w4.z, x2.x, acc0); acc1 = fmaf(w4.z, x2.y, acc1);
            acc2 = fmaf(w4.z, x2.z, acc2); acc3 = fmaf(w4.z, x2.w, acc3);
            acc0 = fmaf(w4.w, x3.x, acc0); acc1 = fmaf(w4.w, x3.y, acc1);
            acc2 = fmaf(w4.w, x3.z, acc2); acc3 = fmaf(w4.w, x3.w, acc3);
        }

        // Recurrent contribution: 32 float4-packed k-steps
        #pragma unroll
        for (int k4 = 0; k4 < K4; ++k4) {
            const float4 w4 = *reinterpret_cast<const float4*>(whh4 + (k4 * Hh + j) * 4);
            const float4 h0 = *reinterpret_cast<const float4*>(hc + (k4 * 4 + 0) * 8);
            const float4 h1 = *reinterpret_cast<const float4*>(hc + (k4 * 4 + 1) * 8);
            const float4 h2 = *reinterpret_cast<const float4*>(hc + (k4 * 4 + 2) * 8);
            const float4 h3 = *reinterpret_cast<const float4*>(hc + (k4 * 4 + 3) * 8);
            acc0 = fmaf(w4.x, h0.x, acc0); acc1 = fmaf(w4.x, h0.y, acc1);
            acc2 = fmaf(w4.x, h0.z, acc2); acc3 = fmaf(w4.x, h0.w, acc3);
            acc0 = fmaf(w4.y, h1.x, acc0); acc1 = fmaf(w4.y, h1.y, acc1);
            acc2 = fmaf(w4.y, h1.z, acc2); acc3 = fmaf(w4.y, h1.w, acc3);
            acc0 = fmaf(w4.z, h2.x, acc0); acc1 = fmaf(w4.z, h2.y, acc1);
            acc2 = fmaf(w4.z, h2.z, acc2); acc3 = fmaf(w4.z, h2.w, acc3);
            acc0 = fmaf(w4.w, h3.x, acc0); acc1 = fmaf(w4.w, h3.y, acc1);
            acc2 = fmaf(w4.w, h3.z, acc2); acc3 = fmaf(w4.w, h3.w, acc3);
        }

        // tanh + store this group's 4 rows of h_new (no reduction needed)
        float4 o;
        o.x = fast_tanh(acc0);
        o.y = fast_tanh(acc1);
        o.z = fast_tanh(acc2);
        o.w = fast_tanh(acc3);
        float* hn = hT + (cur ^ 1) * (Hh * 8) + j * 8 + grp * 4;
        *reinterpret_cast<float4*>(hn) = o;

        // Store prefetched x into the other buffer
        float* xn = xT + (cur ^ 1) * (48 * 8);
        xn[s0] = n0;
        if (a1) xn[s1] = n1;

        __syncthreads();   // one barrier per step
    }

    // ---- Final FC: out[b][o] = b_fc[o] + sum_j W_fc[o][j] * h_last[b][j] ----
    // Tt even -> last h landed in buffer 0.
    const float* hlast = hT;
    for (int idx = tid; idx < NB * Oo; idx += NTH) {
        const int b = idx / Oo;
        const int o = idx - b * Oo;
        const int row = rowBase + b;
        if (row < Bt) {
            float s = b_fc[o];
            const float* wp = W_fc + o * Hh;
            #pragma unroll 8
            for (int jj = 0; jj < Hh; ++jj)
                s = fmaf(wp[jj], hlast[jj * 8 + b], s);
            out[row * Oo + o] = s;
        }
    }
}

extern "C" void kernel_launch(void* const* d_in, const int* in_sizes, int n_in,
                              void* d_out, int out_size)
{
    const float* x   = (const float*)d_in[0];
    const float* Wih = (const float*)d_in[1];
    const float* bih = (const float*)d_in[2];
    const float* Whh = (const float*)d_in[3];
    const float* bhh = (const float*)d_in[4];
    const float* Wfc = (const float*)d_in[5];
    const float* bfc = (const float*)d_in[6];
    float* out = (float*)d_out;

    cudaFuncSetAttribute(rnn_fused_kernel,
                         cudaFuncAttributeMaxDynamicSharedMemorySize, SMEM_BYTES);
    rnn_fused_kernel<<<NBLK, NTH, SMEM_BYTES>>>(x, Wih, bih, Whh, bhh, Wfc, bfc, out);
}

// round 6
// speedup vs baseline: 1.5664x; 1.4489x over previous
#include <cuda_runtime.h>
#include <cstdint>
#include <cstddef>

// Problem dims (fixed by the reference)
#define Bt 1024
#define Tt 512
#define Ii 45
#define Hh 128
#define Oo 45

#define NB  7            // batch rows per CTA
#define NTH 256          // j = tid&127, half = tid>>7 (k-half / i-half split)
#define NBLK ((Bt + NB - 1) / NB)   // 147 CTAs

#define WHH_P 130        // padded row stride for staged W_hh (2-way max conflict, 8B-aligned)
#define WIH_P 50         // padded row stride for staged W_ih

// Shared-memory layout (float offsets; all even -> 8B alignment holds)
#define OFF_WHH  0                           // [j][WHH_P] raw W_hh rows
#define OFF_WIH  (Hh * WHH_P)                // [j][WIH_P] raw W_ih rows (i>=45 zero)
#define OFF_BIAS (OFF_WIH + Hh * WIH_P)      // 128
#define OFF_H    (OFF_BIAS + Hh)             // [2][7][128]  (k contiguous)
#define OFF_X    (OFF_H + 2 * 7 * Hh)        // [2][7][48]   (i contiguous)
#define OFF_PART (OFF_X + 2 * 7 * 48)        // [8][128] ull partials
#define SMEM_FLOATS (OFF_PART + 8 * Hh * 2)
#define SMEM_BYTES  (SMEM_FLOATS * 4)        // ~111 KB

typedef unsigned long long ull;

__device__ __forceinline__ void fma2(ull& acc, ull a, ull b) {
    asm("fma.rn.f32x2 %0, %1, %2, %0;" : "+l"(acc) : "l"(a), "l"(b));
}
__device__ __forceinline__ void add2(ull& acc, ull a) {
    asm("add.rn.f32x2 %0, %0, %1;" : "+l"(acc) : "l"(a));
}
__device__ __forceinline__ float2 unpack2(ull d) {
    unsigned lo, hi;
    asm("mov.b64 {%0, %1}, %2;" : "=r"(lo), "=r"(hi) : "l"(d));
    return make_float2(__uint_as_float(lo), __uint_as_float(hi));
}

// tanh(x) = 1 - 2/(exp(2x)+1): ~1e-6 abs err, exact +/-1 saturation.
__device__ __forceinline__ float fast_tanh(float x) {
    float e = __expf(2.0f * x);
    return 1.0f - __fdividef(2.0f, e + 1.0f);
}

__global__ void __launch_bounds__(NTH, 1)
rnn_fused_kernel(const float* __restrict__ x,
                 const float* __restrict__ W_ih,
                 const float* __restrict__ b_ih,
                 const float* __restrict__ W_hh,
                 const float* __restrict__ b_hh,
                 const float* __restrict__ W_fc,
                 const float* __restrict__ b_fc,
                 float* __restrict__ out)
{
    extern __shared__ float sm[];
    float* whh_s  = sm + OFF_WHH;   // raw rows, padded stride
    float* wih_s  = sm + OFF_WIH;
    float* bias_s = sm + OFF_BIAS;
    float* hT     = sm + OFF_H;     // [buf][row][k]
    float* xT     = sm + OFF_X;     // [buf][row][i48]
    ull*   part   = reinterpret_cast<ull*>(sm + OFF_PART);  // [row][j]

    const int tid  = threadIdx.x;
    const int j    = tid & 127;     // hidden unit owned by this thread
    const int half = tid >> 7;      // 0: k[0,64)/i[0,24), 1: k[64,128)/i[24,48)
    const int rowBase = blockIdx.x * NB;

    // ---- Stage raw weights (coalesced gmem read), bias, zero h/x ----
    for (int idx = tid; idx < Hh * Hh; idx += NTH) {
        int jj = idx >> 7, kk = idx & 127;
        whh_s[jj * WHH_P + kk] = W_hh[idx];
    }
    for (int idx = tid; idx < Hh * 48; idx += NTH) {
        int jj = idx / 48, ii = idx - jj * 48;
        wih_s[jj * WIH_P + ii] = (ii < Ii) ? W_ih[jj * Ii + ii] : 0.0f;
    }
    if (tid < Hh) bias_s[tid] = b_ih[tid] + b_hh[tid];
    for (int idx = tid; idx < 2 * 7 * Hh; idx += NTH) hT[idx] = 0.0f;
    for (int idx = tid; idx < 2 * 7 * 48; idx += NTH) xT[idx] = 0.0f;
    __syncthreads();

    // ---- Pull this thread's weight column slice into registers, packed over k ----
    ull wk2[32], wi2[12];
    {
        const float* wr = whh_s + j * WHH_P + half * 64;
        #pragma unroll
        for (int q = 0; q < 32; ++q)
            wk2[q] = *reinterpret_cast<const ull*>(wr + 2 * q);
        const float* wir = wih_s + j * WIH_P + half * 24;
        #pragma unroll
        for (int q = 0; q < 12; ++q)
            wi2[q] = *reinterpret_cast<const ull*>(wir + 2 * q);
    }
    const float bi = bias_s[j];

    // ---- x stager: 256 threads cover NB*Ii = 315 elems (<=2 each) ----
    const int e0 = tid, e1 = tid + NTH;
    const bool a1 = e1 < NB * Ii;                 // e0 < 315 always
    const int b0 = e0 / Ii, b1 = a1 ? e1 / Ii : 0;
    const int i0 = e0 - b0 * Ii, i1 = e1 - b1 * Ii;
    const bool val0 = (rowBase + b0 < Bt);
    const bool val1 = a1 && (rowBase + b1 < Bt);
    const float* g0 = x + ((size_t)(rowBase + b0) * Tt) * Ii + i0;
    const float* g1 = x + ((size_t)(rowBase + b1) * Tt) * Ii + i1;
    const int s0 = b0 * 48 + i0, s1 = b1 * 48 + i1;   // [row][i] layout

    // Stage x for t = 0 into buffer 0
    xT[s0] = val0 ? g0[0] : 0.0f;
    if (a1) xT[s1] = val1 ? g1[0] : 0.0f;
    __syncthreads();

    // bias enters once, in half0 lane-lo of the packed accumulator
    const ull binit = (half == 0) ? (ull)__float_as_uint(bi) : 0ull;

    for (int t = 0; t < Tt; ++t) {
        const int cur = t & 1;
        const float* hc = hT + cur * (7 * Hh) + half * 64;   // this half's k slice
        const float* xc = xT + cur * (7 * 48) + half * 24;   // this half's i slice

        // Prefetch next-step x (hidden behind the FMA loops)
        float n0 = 0.0f, n1 = 0.0f;
        if (t + 1 < Tt) {
            const int off = (t + 1) * Ii;
            if (val0) n0 = g0[off];
            if (val1) n1 = g1[off];
        }

        // Packed accumulators per batch row: lanes = (even-k sum, odd-k sum)
        ull acc0 = binit, acc1 = binit, acc2 = binit, acc3 = binit;
        ull acc4 = binit, acc5 = binit, acc6 = binit;

        // Input contribution: 6 i-quads, broadcast LDS.128 per (row, quad)
        #pragma unroll
        for (int q = 0; q < 6; ++q) {
            const ull w0 = wi2[2 * q], w1 = wi2[2 * q + 1];
            ulonglong2 v;
            v = *reinterpret_cast<const ulonglong2*>(xc + 0 * 48 + q * 4);
            fma2(acc0, w0, v.x); fma2(acc0, w1, v.y);
            v = *reinterpret_cast<const ulonglong2*>(xc + 1 * 48 + q * 4);
            fma2(acc1, w0, v.x); fma2(acc1, w1, v.y);
            v = *reinterpret_cast<const ulonglong2*>(xc + 2 * 48 + q * 4);
            fma2(acc2, w0, v.x); fma2(acc2, w1, v.y);
            v = *reinterpret_cast<const ulonglong2*>(xc + 3 * 48 + q * 4);
            fma2(acc3, w0, v.x); fma2(acc3, w1, v.y);
            v = *reinterpret_cast<const ulonglong2*>(xc + 4 * 48 + q * 4);
            fma2(acc4, w0, v.x); fma2(acc4, w1, v.y);
            v = *reinterpret_cast<const ulonglong2*>(xc + 5 * 48 + q * 4);
            fma2(acc5, w0, v.x); fma2(acc5, w1, v.y);
            v = *reinterpret_cast<const ulonglong2*>(xc + 6 * 48 + q * 4);
            fma2(acc6, w0, v.x); fma2(acc6, w1, v.y);
        }

        // Recurrent contribution: 16 k-quads
        #pragma unroll
        for (int q = 0; q < 16; ++q) {
            const ull w0 = wk2[2 * q], w1 = wk2[2 * q + 1];
            ulonglong2 v;
            v = *reinterpret_cast<const ulonglong2*>(hc + 0 * Hh + q * 4);
            fma2(acc0, w0, v.x); fma2(acc0, w1, v.y);
            v = *reinterpret_cast<const ulonglong2*>(hc + 1 * Hh + q * 4);
            fma2(acc1, w0, v.x); fma2(acc1, w1, v.y);
            v = *reinterpret_cast<const ulonglong2*>(hc + 2 * Hh + q * 4);
            fma2(acc2, w0, v.x); fma2(acc2, w1, v.y);
            v = *reinterpret_cast<const ulonglong2*>(hc + 3 * Hh + q * 4);
            fma2(acc3, w0, v.x); fma2(acc3, w1, v.y);
            v = *reinterpret_cast<const ulonglong2*>(hc + 4 * Hh + q * 4);
            fma2(acc4, w0, v.x); fma2(acc4, w1, v.y);
            v = *reinterpret_cast<const ulonglong2*>(hc + 5 * Hh + q * 4);
            fma2(acc5, w0, v.x); fma2(acc5, w1, v.y);
            v = *reinterpret_cast<const ulonglong2*>(hc + 6 * Hh + q * 4);
            fma2(acc6, w0, v.x); fma2(acc6, w1, v.y);
        }

        // Cross-half exchange: half1 posts rows 0-3, half0 posts rows 4-6
        if (half) {
            part[0 * Hh + j] = acc0;
            part[1 * Hh + j] = acc1;
            part[2 * Hh + j] = acc2;
            part[3 * Hh + j] = acc3;
        } else {
            part[4 * Hh + j] = acc4;
            part[5 * Hh + j] = acc5;
            part[6 * Hh + j] = acc6;
        }
        __syncthreads();

        // Finish: half0 -> rows 0-3, half1 -> rows 4-6 (balanced tanh work)
        float* hn = hT + (cur ^ 1) * (7 * Hh);
        if (!half) {
            add2(acc0, part[0 * Hh + j]);
            add2(acc1, part[1 * Hh + j]);
            add2(acc2, part[2 * Hh + j]);
            add2(acc3, part[3 * Hh + j]);
            float2 f0 = unpack2(acc0), f1 = unpack2(acc1);
            float2 f2 = unpack2(acc2), f3 = unpack2(acc3);
            hn[0 * Hh + j] = fast_tanh(f0.x + f0.y);
            hn[1 * Hh + j] = fast_tanh(f1.x + f1.y);
            hn[2 * Hh + j] = fast_tanh(f2.x + f2.y);
            hn[3 * Hh + j] = fast_tanh(f3.x + f3.y);
        } else {
            add2(acc4, part[4 * Hh + j]);
            add2(acc5, part[5 * Hh + j]);
            add2(acc6, part[6 * Hh + j]);
            float2 f4 = unpack2(acc4), f5 = unpack2(acc5), f6 = unpack2(acc6);
            hn[4 * Hh + j] = fast_tanh(f4.x + f4.y);
            hn[5 * Hh + j] = fast_tanh(f5.x + f5.y);
            hn[6 * Hh + j] = fast_tanh(f6.x + f6.y);
        }

        // Store prefetched x into the other buffer (pads stay 0)
        float* xn = xT + (cur ^ 1) * (7 * 48);
        xn[s0] = n0;
        if (a1) xn[s1] = n1;

        __syncthreads();
    }

    // ---- Final FC: out[b][o] = b_fc[o] + sum_j W_fc[o][j] * h_last[b][j] ----
    // Tt even -> last h landed in buffer 0. Layout [row][j], contiguous in j.
    const float* hlast = hT;
    for (int idx = tid; idx < NB * Oo; idx += NTH) {
        const int b = idx / Oo;
        const int o = idx - b * Oo;
        const int row = rowBase + b;
        if (row < Bt) {
            float s = b_fc[o];
            const float* wp = W_fc + o * Hh;
            const float* hp = hlast + b * Hh;
            #pragma unroll 8
            for (int jj = 0; jj < Hh; ++jj)
                s = fmaf(wp[jj], hp[jj], s);
            out[row * Oo + o] = s;
        }
    }
}

extern "C" void kernel_launch(void* const* d_in, const int* in_sizes, int n_in,
                              void* d_out, int out_size)
{
    const float* x   = (const float*)d_in[0];
    const float* Wih = (const float*)d_in[1];
    const float* bih = (const float*)d_in[2];
    const float* Whh = (const float*)d_in[3];
    const float* bhh = (const float*)d_in[4];
    const float* Wfc = (const float*)d_in[5];
    const float* bfc = (const float*)d_in[6];
    float* out = (float*)d_out;

    cudaFuncSetAttribute(rnn_fused_kernel,
                         cudaFuncAttributeMaxDynamicSharedMemorySize, SMEM_BYTES);
    rnn_fused_kernel<<<NBLK, NTH, SMEM_BYTES>>>(x, Wih, bih, Whh, bhh, Wfc, bfc, out);
}